// round 8
// baseline (speedup 1.0000x reference)
#include <cuda_runtime.h>
#include <math.h>

// Problem shape (fixed by the dataset problem)
#define NB    2
#define LSEQ  2048
#define DIM   512
#define NH    8
#define HD    64
#define MROWS (NB*LSEQ)      // 4096
#define CHUNK 64
#define NCH   (LSEQ/CHUNK)   // 32
#define NHEAD (NB*NH)        // 16
#define SROW  68             // 64 D cols + z col @64, padded to 16B multiple
#define SSIZE (64*SROW)      // 4352 floats per chunk-state

// Scratch (device globals: allocation-free rule). 16B-aligned for float4 access.
__device__ __align__(16) float g_q[MROWS*DIM];
__device__ __align__(16) float g_k[MROWS*DIM];
__device__ __align__(16) float g_v[MROWS*DIM];
__device__ __align__(16) float g_S[NHEAD*NCH*SSIZE];

__device__ __forceinline__ float softplus_f(float x){
    return (x > 20.0f) ? x : log1pf(expf(x));
}

// ---- packed f32x2 FMA helpers (sm_103a) ----
__device__ __forceinline__ unsigned long long pack2(float lo, float hi){
    unsigned long long r;
    asm("mov.b64 %0, {%1,%2};" : "=l"(r) : "f"(lo), "f"(hi));
    return r;
}
__device__ __forceinline__ void fma2(unsigned long long& d, unsigned long long a, unsigned long long b){
    asm("fma.rn.f32x2 %0, %1, %2, %0;" : "+l"(d) : "l"(a), "l"(b));
}
__device__ __forceinline__ float2 unpack2(unsigned long long v){
    float2 r;
    asm("mov.b64 {%0,%1}, %2;" : "=f"(r.x), "=f"(r.y) : "l"(v));
    return r;
}

// ============================================================
// Kernel 1: fused QKV projections.  O[m][n] = sum_k X[m][k]*W[n][k]
// grid.z selects (query,Wq,softplus) / (key,Wk,softplus) / (key,Wv,linear)
// 64x64 tile per block, BK=16, 256 threads, 4x4 per thread via f32x2.
// ============================================================
__global__ __launch_bounds__(256) void proj_kernel(
    const float* __restrict__ query, const float* __restrict__ keyseq,
    const float* __restrict__ Wq, const float* __restrict__ Wk,
    const float* __restrict__ Wv)
{
    int z = blockIdx.z;
    const float* X = (z==0) ? query : keyseq;
    const float* W = (z==0) ? Wq : (z==1 ? Wk : Wv);
    float* O       = (z==0) ? g_q : (z==1 ? g_k : g_v);
    bool act = (z < 2);

    __shared__ float As[16][68];
    __shared__ float Bs[16][68];

    int tid = threadIdx.x;
    int ty = tid >> 4, tx = tid & 15;
    int ty4 = ty*4, tx4 = tx*4;
    int lrow = tid >> 2, lk4 = (tid & 3)*4;
    int m0 = blockIdx.y * 64, n0 = blockIdx.x * 64;

    const float* Xp = X + (m0+lrow)*DIM + lk4;
    const float* Wp = W + (n0+lrow)*DIM + lk4;

    unsigned long long acc2[4][2] = {};

    for (int kt = 0; kt < DIM; kt += 16){
        float4 a = *(const float4*)(Xp + kt);
        float4 b = *(const float4*)(Wp + kt);
        As[lk4+0][lrow]=a.x; As[lk4+1][lrow]=a.y; As[lk4+2][lrow]=a.z; As[lk4+3][lrow]=a.w;
        Bs[lk4+0][lrow]=b.x; Bs[lk4+1][lrow]=b.y; Bs[lk4+2][lrow]=b.z; Bs[lk4+3][lrow]=b.w;
        __syncthreads();
        #pragma unroll
        for (int k = 0; k < 16; k++){
            unsigned long long b01 = *(const unsigned long long*)&Bs[k][tx4];
            unsigned long long b23 = *(const unsigned long long*)&Bs[k][tx4+2];
            #pragma unroll
            for (int i = 0; i < 4; i++){
                float av = As[k][ty4+i];
                unsigned long long a2 = pack2(av, av);
                fma2(acc2[i][0], a2, b01);
                fma2(acc2[i][1], a2, b23);
            }
        }
        __syncthreads();
    }
    #pragma unroll
    for (int i = 0; i < 4; i++){
        float2 v01 = unpack2(acc2[i][0]);
        float2 v23 = unpack2(acc2[i][1]);
        float vals[4] = {v01.x, v01.y, v23.x, v23.y};
        float* orow = O + (m0+ty4+i)*DIM + n0 + tx4;
        #pragma unroll
        for (int j = 0; j < 4; j++)
            orow[j] = act ? softplus_f(vals[j]) : vals[j];
    }
}

// ============================================================
// Kernel 2: per-chunk state  S_c[d][D] = sum_j pk[j][d]*v[j][D] ; S_c[d][64]=sum_j pk[j][d]
// one block per (head, chunk); 256 threads
// ============================================================
__global__ __launch_bounds__(256) void chunk_kv_kernel(){
    int bid = blockIdx.x;
    int head = bid >> 5, chunk = bid & 31;
    int n = head >> 3, h = head & 7;
    int row0 = n*LSEQ + chunk*CHUNK;
    int col  = h*HD;

    __shared__ float Ks[64*64];
    __shared__ float Vs[64*64];
    int tid = threadIdx.x;
    {
        int r = tid >> 2, c0 = (tid & 3)*16;
        #pragma unroll
        for (int t = 0; t < 4; t++){
            float4 kv = *(const float4*)(g_k + (row0+r)*DIM + col + c0 + t*4);
            float4 vv = *(const float4*)(g_v + (row0+r)*DIM + col + c0 + t*4);
            *(float4*)&Ks[r*64 + c0 + t*4] = kv;
            *(float4*)&Vs[r*64 + c0 + t*4] = vv;
        }
    }
    __syncthreads();

    int d = tid >> 2, lane = tid & 3;
    float acc[16];
    #pragma unroll
    for (int i = 0; i < 16; i++) acc[i] = 0.f;
    float zk = 0.f;
    for (int j = 0; j < 64; j++){
        float kd = Ks[j*64 + d];
        zk += kd;
        #pragma unroll
        for (int i = 0; i < 16; i++) acc[i] += kd * Vs[j*64 + lane + 4*i];
    }
    float* Sp = g_S + (head*NCH + chunk)*SSIZE + d*SROW;
    #pragma unroll
    for (int i = 0; i < 16; i++) Sp[lane + 4*i] = acc[i];
    if (lane == 0) Sp[64] = zk;
}

// ============================================================
// Kernel 3: exclusive prefix over chunk states (per head, 32 chunks)
// ============================================================
__global__ __launch_bounds__(256) void scan_kernel(){
    int head = blockIdx.x;
    float* base = g_S + head*NCH*SSIZE;
    for (int e = threadIdx.x; e < SSIZE; e += 256){
        float run = 0.f;
        for (int c = 0; c < NCH; c++){
            float* p = base + c*SSIZE + e;
            float t = *p; *p = run; run += t;
        }
    }
}

// ============================================================
// Kernel 4: output.  out[q][D] = (pq_q . S_prefix[:,D] + sum_{j<=q} (pq_q.pk_j) v[j][D]) / z
// one block per (head, chunk); thread: q = tid/4, 16 D-cols each. pq row in registers.
// ============================================================
__global__ __launch_bounds__(256) void attn_kernel(float* __restrict__ out){
    int bid = blockIdx.x;
    int head = bid >> 5, chunk = bid & 31;
    int n = head >> 3, h = head & 7;
    int row0 = n*LSEQ + chunk*CHUNK;
    int col  = h*HD;

    __shared__ float U[8192];   // phase1: S prefix (4352) ; phase2: pk (4096) + v (4096)
    int tid = threadIdx.x;
    int qi = tid >> 2, lane = tid & 3;
    int Db = lane*16;

    // pq row -> registers
    float pq[64];
    const float* qrow = g_q + (row0+qi)*DIM + col;
    #pragma unroll
    for (int t = 0; t < 16; t++){
        float4 f = *(const float4*)(qrow + t*4);
        pq[t*4+0]=f.x; pq[t*4+1]=f.y; pq[t*4+2]=f.z; pq[t*4+3]=f.w;
    }

    // load S prefix
    const float* Sp = g_S + (head*NCH + chunk)*SSIZE;
    for (int e = tid; e < SSIZE; e += 256) U[e] = Sp[e];
    __syncthreads();

    float acc[16];
    #pragma unroll
    for (int i = 0; i < 16; i++) acc[i] = 0.f;
    float z = 0.f;

    // inter-chunk: pq . S
    #pragma unroll
    for (int dd = 0; dd < 64; dd++){
        float a = pq[dd];
        const float* Srow = &U[dd*SROW];
        float4 s0 = *(const float4*)(Srow + Db + 0);
        float4 s1 = *(const float4*)(Srow + Db + 4);
        float4 s2 = *(const float4*)(Srow + Db + 8);
        float4 s3 = *(const float4*)(Srow + Db + 12);
        acc[0]+=a*s0.x; acc[1]+=a*s0.y; acc[2]+=a*s0.z; acc[3]+=a*s0.w;
        acc[4]+=a*s1.x; acc[5]+=a*s1.y; acc[6]+=a*s1.z; acc[7]+=a*s1.w;
        acc[8]+=a*s2.x; acc[9]+=a*s2.y; acc[10]+=a*s2.z; acc[11]+=a*s2.w;
        acc[12]+=a*s3.x; acc[13]+=a*s3.y; acc[14]+=a*s3.z; acc[15]+=a*s3.w;
        z += a * Srow[64];
    }
    __syncthreads();

    // load pk, v chunk tiles
    {
        int r = tid >> 2, c0 = (tid & 3)*16;
        #pragma unroll
        for (int t = 0; t < 4; t++){
            float4 kv = *(const float4*)(g_k + (row0+r)*DIM + col + c0 + t*4);
            float4 vv = *(const float4*)(g_v + (row0+r)*DIM + col + c0 + t*4);
            *(float4*)&U[r*64 + c0 + t*4] = kv;
            *(float4*)&U[4096 + r*64 + c0 + t*4] = vv;
        }
    }
    __syncthreads();

    // intra-chunk causal part
    for (int j = 0; j <= qi; j++){
        const float* krow = &U[j*64];
        float a0=0.f, a1=0.f, a2=0.f, a3=0.f;
        #pragma unroll
        for (int dd = 0; dd < 64; dd += 4){
            a0 += pq[dd+0]*krow[dd+0];
            a1 += pq[dd+1]*krow[dd+1];
            a2 += pq[dd+2]*krow[dd+2];
            a3 += pq[dd+3]*krow[dd+3];
        }
        float a = (a0+a1)+(a2+a3);
        z += a;
        const float* vrow = &U[4096 + j*64];
        #pragma unroll
        for (int t = 0; t < 4; t++){
            float4 vv = *(const float4*)(vrow + Db + t*4);
            acc[t*4+0] += a*vv.x; acc[t*4+1] += a*vv.y;
            acc[t*4+2] += a*vv.z; acc[t*4+3] += a*vv.w;
        }
    }

    float inv = 1.0f / z;
    float* orow = out + (row0+qi)*DIM + col + Db;
    #pragma unroll
    for (int i = 0; i < 16; i++) orow[i] = acc[i]*inv;
}

extern "C" void kernel_launch(void* const* d_in, const int* in_sizes, int n_in,
                              void* d_out, int out_size){
    const float* query  = (const float*)d_in[0];
    const float* keyseq = (const float*)d_in[1];
    const float* Wq     = (const float*)d_in[2];
    const float* Wk     = (const float*)d_in[3];
    const float* Wv     = (const float*)d_in[4];
    float* out = (float*)d_out;

    dim3 g1(DIM/64, MROWS/64, 3);
    proj_kernel<<<g1, 256>>>(query, keyseq, Wq, Wk, Wv);
    chunk_kv_kernel<<<NHEAD*NCH, 256>>>();
    scan_kernel<<<NHEAD, 256>>>();
    attn_kernel<<<NHEAD*NCH, 256>>>(out);
}

// round 10
// speedup vs baseline: 2.2198x; 2.2198x over previous
#include <cuda_runtime.h>
#include <math.h>

#define NB    2
#define LSEQ  2048
#define DIM   512
#define NH    8
#define HD    64
#define MROWS (NB*LSEQ)      // 4096
#define CHUNK 64
#define NCH   (LSEQ/CHUNK)   // 32
#define NHEAD (NB*NH)        // 16
#define SROW  68             // 64 D cols + z col @64
#define SSIZE (64*SROW)      // 4352 floats per chunk-state

typedef unsigned long long ull;

__device__ __align__(16) float g_q[MROWS*DIM];
__device__ __align__(16) float g_k[MROWS*DIM];
__device__ __align__(16) float g_v[MROWS*DIM];
__device__ __align__(16) float g_S[NHEAD*NCH*SSIZE];

__device__ __forceinline__ float softplus_f(float x){
    return (x > 20.0f) ? x : log1pf(expf(x));
}
__device__ __forceinline__ ull pack2(float lo, float hi){
    ull r; asm("mov.b64 %0, {%1,%2};" : "=l"(r) : "f"(lo), "f"(hi)); return r;
}
__device__ __forceinline__ void fma2(ull& d, ull a, ull b){
    asm("fma.rn.f32x2 %0, %1, %2, %0;" : "+l"(d) : "l"(a), "l"(b));
}
__device__ __forceinline__ float2 unpack2(ull v){
    float2 r; asm("mov.b64 {%0,%1}, %2;" : "=f"(r.x), "=f"(r.y) : "l"(v)); return r;
}

// ============================================================
// Kernel 1: fused QKV projections (UNCHANGED from passing R8 baseline)
// ============================================================
__global__ __launch_bounds__(256) void proj_kernel(
    const float* __restrict__ query, const float* __restrict__ keyseq,
    const float* __restrict__ Wq, const float* __restrict__ Wk,
    const float* __restrict__ Wv)
{
    int z = blockIdx.z;
    const float* X = (z==0) ? query : keyseq;
    const float* W = (z==0) ? Wq : (z==1 ? Wk : Wv);
    float* O       = (z==0) ? g_q : (z==1 ? g_k : g_v);
    bool act = (z < 2);

    __shared__ float As[16][68];
    __shared__ float Bs[16][68];

    int tid = threadIdx.x;
    int ty = tid >> 4, tx = tid & 15;
    int ty4 = ty*4, tx4 = tx*4;
    int lrow = tid >> 2, lk4 = (tid & 3)*4;
    int m0 = blockIdx.y * 64, n0 = blockIdx.x * 64;

    const float* Xp = X + (m0+lrow)*DIM + lk4;
    const float* Wp = W + (n0+lrow)*DIM + lk4;

    ull acc2[4][2] = {};

    for (int kt = 0; kt < DIM; kt += 16){
        float4 a = *(const float4*)(Xp + kt);
        float4 b = *(const float4*)(Wp + kt);
        As[lk4+0][lrow]=a.x; As[lk4+1][lrow]=a.y; As[lk4+2][lrow]=a.z; As[lk4+3][lrow]=a.w;
        Bs[lk4+0][lrow]=b.x; Bs[lk4+1][lrow]=b.y; Bs[lk4+2][lrow]=b.z; Bs[lk4+3][lrow]=b.w;
        __syncthreads();
        #pragma unroll
        for (int k = 0; k < 16; k++){
            ull b01 = *(const ull*)&Bs[k][tx4];
            ull b23 = *(const ull*)&Bs[k][tx4+2];
            #pragma unroll
            for (int i = 0; i < 4; i++){
                float av = As[k][ty4+i];
                ull a2 = pack2(av, av);
                fma2(acc2[i][0], a2, b01);
                fma2(acc2[i][1], a2, b23);
            }
        }
        __syncthreads();
    }
    #pragma unroll
    for (int i = 0; i < 4; i++){
        float2 v01 = unpack2(acc2[i][0]);
        float2 v23 = unpack2(acc2[i][1]);
        float vals[4] = {v01.x, v01.y, v23.x, v23.y};
        float* orow = O + (m0+ty4+i)*DIM + n0 + tx4;
        #pragma unroll
        for (int j = 0; j < 4; j++)
            orow[j] = act ? softplus_f(vals[j]) : vals[j];
    }
}

// ============================================================
// Kernel 2: per-chunk state, register-tiled GEMM.
// S_c[d][D] = sum_j K[j][d]*V[j][D] ; S_c[d][64] = sum_j K[j][d]
// ============================================================
__global__ __launch_bounds__(256) void chunk_kv_kernel(){
    int bid = blockIdx.x;
    int head = bid >> 5, chunk = bid & 31;
    int n = head >> 3, h = head & 7;
    int row0 = n*LSEQ + chunk*CHUNK;
    int col  = h*HD;

    __shared__ float Ks[64*68];
    __shared__ float Vs[64*68];
    int tid = threadIdx.x;
    {
        int r = tid >> 2, c0 = (tid & 3)*16;
        const float* kr = g_k + (row0+r)*DIM + col;
        const float* vr = g_v + (row0+r)*DIM + col;
        #pragma unroll
        for (int t = 0; t < 4; t++){
            *(float4*)&Ks[r*68 + c0 + t*4] = *(const float4*)(kr + c0 + t*4);
            *(float4*)&Vs[r*68 + c0 + t*4] = *(const float4*)(vr + c0 + t*4);
        }
    }
    __syncthreads();

    int ty = tid >> 4, tx = tid & 15;
    int ty4 = ty*4, tx4 = tx*4;

    ull acc[4][2] = {};
    #pragma unroll 8
    for (int j = 0; j < 64; j++){
        ull b01 = *(const ull*)&Vs[j*68 + tx4];
        ull b23 = *(const ull*)&Vs[j*68 + tx4 + 2];
        #pragma unroll
        for (int i = 0; i < 4; i++){
            float av = Ks[j*68 + ty4 + i];
            ull a2 = pack2(av, av);
            fma2(acc[i][0], a2, b01);
            fma2(acc[i][1], a2, b23);
        }
    }

    float* Sp = g_S + (head*NCH + chunk)*SSIZE;
    #pragma unroll
    for (int i = 0; i < 4; i++){
        float2 v01 = unpack2(acc[i][0]);
        float2 v23 = unpack2(acc[i][1]);
        float* row = Sp + (ty4+i)*SROW + tx4;
        row[0]=v01.x; row[1]=v01.y; row[2]=v23.x; row[3]=v23.y;
    }
    if (tid < 64){
        float s = 0.f;
        #pragma unroll 8
        for (int j = 0; j < 64; j++) s += Ks[j*68 + tid];
        Sp[tid*SROW + 64] = s;
    }
}

// ============================================================
// Kernel 3: exclusive prefix over chunk states. 272 blocks, prefetch-all.
// ============================================================
__global__ __launch_bounds__(256) void scan_kernel(){
    int head = blockIdx.x / 17, part = blockIdx.x % 17;
    int e = part*256 + threadIdx.x;   // 17*256 = 4352 = SSIZE exactly
    float* base = g_S + head*NCH*SSIZE + e;
    float vals[NCH];
    #pragma unroll
    for (int c = 0; c < NCH; c++) vals[c] = base[c*SSIZE];
    float run = 0.f;
    #pragma unroll
    for (int c = 0; c < NCH; c++){ base[c*SSIZE] = run; run += vals[c]; }
}

// ============================================================
// Kernel 4: output via three cooperative 64x64x64 GEMM stages.
//  inter:  O  = P @ S_pref          (P_T, S_pref in smem)
//  stage1: S1 = P @ K^T, causal-masked, written transposed over P_T
//  stage2: O += S1 @ V
//  z[q] = P.S_pref_z + rowsum(S1m); out = O/z
// dynamic smem: P_T | BA (S_pref -> K_T) | BV (V) | zq   = 52480 B
// ============================================================
#define ATT_SMEM ((3*SSIZE + 64)*4)

__global__ __launch_bounds__(256) void attn_kernel(float* __restrict__ out){
    extern __shared__ float U[];
    float* PT = U;              // P_T[d][q], later S1_T[j][q]
    float* BA = U + SSIZE;      // S_pref (d-major, z at col 64), later K_T[d][j]
    float* BV = U + 2*SSIZE;    // V row-major  j x 68
    float* zq = U + 3*SSIZE;    // 64

    int bid = blockIdx.x;
    int head = bid >> 5, chunk = bid & 31;
    int n = head >> 3, h = head & 7;
    int row0 = n*LSEQ + chunk*CHUNK;
    int col  = h*HD;

    int tid = threadIdx.x;
    int ty = tid >> 4, tx = tid & 15;
    int ty4 = ty*4, tx4 = tx*4;

    // load P_T (transposed q-chunk): thread r=tid&63 owns row r, 16 cols
    {
        int r = tid & 63, cb = (tid >> 6)*16;
        const float* qrow = g_q + (row0+r)*DIM + col + cb;
        #pragma unroll
        for (int t = 0; t < 4; t++){
            float4 f = *(const float4*)(qrow + t*4);
            int c = cb + t*4;
            PT[(c+0)*68+r]=f.x; PT[(c+1)*68+r]=f.y;
            PT[(c+2)*68+r]=f.z; PT[(c+3)*68+r]=f.w;
        }
    }
    // load S_pref (layout matches smem stride exactly)
    {
        const float* Sp = g_S + (head*NCH + chunk)*SSIZE;
        for (int e = tid*4; e < SSIZE; e += 1024)
            *(float4*)&BA[e] = *(const float4*)&Sp[e];
    }
    __syncthreads();

    // inter-chunk GEMM: acc = P @ S_pref
    ull acc[4][2] = {};
    #pragma unroll 8
    for (int d = 0; d < 64; d++){
        ull b01 = *(const ull*)&BA[d*68 + tx4];
        ull b23 = *(const ull*)&BA[d*68 + tx4 + 2];
        #pragma unroll
        for (int i = 0; i < 4; i++){
            float av = PT[d*68 + ty4 + i];
            ull a2 = pack2(av, av);
            fma2(acc[i][0], a2, b01);
            fma2(acc[i][1], a2, b23);
        }
    }
    if (tid < 64){
        float s = 0.f;
        #pragma unroll 8
        for (int d = 0; d < 64; d++) s += PT[d*68 + tid] * BA[d*68 + 64];
        zq[tid] = s;
    }
    __syncthreads();   // BA consumed

    // load K_T into BA, V into BV
    {
        int r = tid & 63, cb = (tid >> 6)*16;
        const float* krow = g_k + (row0+r)*DIM + col + cb;
        #pragma unroll
        for (int t = 0; t < 4; t++){
            float4 f = *(const float4*)(krow + t*4);
            int c = cb + t*4;
            BA[(c+0)*68+r]=f.x; BA[(c+1)*68+r]=f.y;
            BA[(c+2)*68+r]=f.z; BA[(c+3)*68+r]=f.w;
        }
        int r2 = tid >> 2, c2 = (tid & 3)*16;
        const float* vrow = g_v + (row0+r2)*DIM + col;
        #pragma unroll
        for (int t = 0; t < 4; t++)
            *(float4*)&BV[r2*68 + c2 + t*4] = *(const float4*)(vrow + c2 + t*4);
    }
    __syncthreads();

    // stage1: S1[q][j] = P @ K^T
    ull accb[4][2] = {};
    #pragma unroll 8
    for (int d = 0; d < 64; d++){
        ull b01 = *(const ull*)&BA[d*68 + tx4];
        ull b23 = *(const ull*)&BA[d*68 + tx4 + 2];
        #pragma unroll
        for (int i = 0; i < 4; i++){
            float av = PT[d*68 + ty4 + i];
            ull a2 = pack2(av, av);
            fma2(accb[i][0], a2, b01);
            fma2(accb[i][1], a2, b23);
        }
    }
    __syncthreads();   // all PT reads done before overwrite

    // masked write S1_T over PT
    #pragma unroll
    for (int i = 0; i < 4; i++){
        float2 v01 = unpack2(accb[i][0]);
        float2 v23 = unpack2(accb[i][1]);
        float vv[4] = {v01.x, v01.y, v23.x, v23.y};
        int q = ty4 + i;
        #pragma unroll
        for (int jj = 0; jj < 4; jj++){
            int j = tx4 + jj;
            PT[j*68 + q] = (j <= q) ? vv[jj] : 0.f;
        }
    }
    __syncthreads();
    if (tid < 64){
        float s = 0.f;
        #pragma unroll 8
        for (int j = 0; j < 64; j++) s += PT[j*68 + tid];
        zq[tid] += s;
    }
    __syncthreads();

    // stage2: acc += S1m @ V
    #pragma unroll 8
    for (int j = 0; j < 64; j++){
        ull b01 = *(const ull*)&BV[j*68 + tx4];
        ull b23 = *(const ull*)&BV[j*68 + tx4 + 2];
        #pragma unroll
        for (int i = 0; i < 4; i++){
            float av = PT[j*68 + ty4 + i];
            ull a2 = pack2(av, av);
            fma2(acc[i][0], a2, b01);
            fma2(acc[i][1], a2, b23);
        }
    }

    // write normalized output
    #pragma unroll
    for (int i = 0; i < 4; i++){
        int q = ty4 + i;
        float inv = 1.0f / zq[q];
        float2 v01 = unpack2(acc[i][0]);
        float2 v23 = unpack2(acc[i][1]);
        float* orow = out + (row0+q)*DIM + col + tx4;
        orow[0]=v01.x*inv; orow[1]=v01.y*inv; orow[2]=v23.x*inv; orow[3]=v23.y*inv;
    }
}

extern "C" void kernel_launch(void* const* d_in, const int* in_sizes, int n_in,
                              void* d_out, int out_size){
    const float* query  = (const float*)d_in[0];
    const float* keyseq = (const float*)d_in[1];
    const float* Wq     = (const float*)d_in[2];
    const float* Wk     = (const float*)d_in[3];
    const float* Wv     = (const float*)d_in[4];
    float* out = (float*)d_out;

    cudaFuncSetAttribute(attn_kernel, cudaFuncAttributeMaxDynamicSharedMemorySize, ATT_SMEM);

    dim3 g1(DIM/64, MROWS/64, 3);
    proj_kernel<<<g1, 256>>>(query, keyseq, Wq, Wk, Wv);
    chunk_kv_kernel<<<NHEAD*NCH, 256>>>();
    scan_kernel<<<NHEAD*17, 256>>>();
    attn_kernel<<<NHEAD*NCH, 256, ATT_SMEM>>>(out);
}

// round 12
// speedup vs baseline: 3.2071x; 1.4448x over previous
#include <cuda_runtime.h>
#include <cuda_bf16.h>
#include <math.h>

#define NB    2
#define LSEQ  2048
#define DIM   512
#define NH    8
#define HD    64
#define MROWS (NB*LSEQ)      // 4096
#define CHUNK 64
#define NCH   (LSEQ/CHUNK)   // 32
#define NHEAD (NB*NH)        // 16
#define SROW  68
#define SSIZE (64*SROW)      // 4352

typedef unsigned long long ull;
typedef unsigned int u32;

__device__ __align__(16) float g_q[MROWS*DIM];
__device__ __align__(16) float g_k[MROWS*DIM];
__device__ __align__(16) float g_v[MROWS*DIM];
__device__ __align__(16) float g_S[NHEAD*NCH*SSIZE];

// bf16 hi/lo split operands
__device__ __align__(16) __nv_bfloat16 g_qh[MROWS*DIM], g_ql[MROWS*DIM];
__device__ __align__(16) __nv_bfloat16 g_kh[MROWS*DIM], g_kl[MROWS*DIM];
__device__ __align__(16) __nv_bfloat16 g_wh[3*DIM*DIM], g_wl[3*DIM*DIM];

__device__ __forceinline__ float softplus_f(float x){
    return (x > 20.0f) ? x : log1pf(expf(x));
}
__device__ __forceinline__ ull pack2(float lo, float hi){
    ull r; asm("mov.b64 %0, {%1,%2};" : "=l"(r) : "f"(lo), "f"(hi)); return r;
}
__device__ __forceinline__ void fma2(ull& d, ull a, ull b){
    asm("fma.rn.f32x2 %0, %1, %2, %0;" : "+l"(d) : "l"(a), "l"(b));
}
__device__ __forceinline__ float2 unpack2(ull v){
    float2 r; asm("mov.b64 {%0,%1}, %2;" : "=f"(r.x), "=f"(r.y) : "l"(v)); return r;
}
__device__ __forceinline__ void mma_bf16(float* d, u32 a0,u32 a1,u32 a2,u32 a3, u32 b0,u32 b1){
    asm("mma.sync.aligned.m16n8k16.row.col.f32.bf16.bf16.f32 "
        "{%0,%1,%2,%3}, {%4,%5,%6,%7}, {%8,%9}, {%0,%1,%2,%3};"
        : "+f"(d[0]),"+f"(d[1]),"+f"(d[2]),"+f"(d[3])
        : "r"(a0),"r"(a1),"r"(a2),"r"(a3),"r"(b0),"r"(b1));
}

// ============================================================
// Kernel 0: fp32 -> bf16 hi/lo split
// ============================================================
__global__ __launch_bounds__(256) void cvt_kernel(
    const float* __restrict__ src, __nv_bfloat16* __restrict__ hi,
    __nv_bfloat16* __restrict__ lo, int n4)
{
    int i = blockIdx.x*blockDim.x + threadIdx.x;
    if (i >= n4) return;
    float4 f = ((const float4*)src)[i];
    __nv_bfloat16 h0=__float2bfloat16(f.x), h1=__float2bfloat16(f.y),
                  h2=__float2bfloat16(f.z), h3=__float2bfloat16(f.w);
    __nv_bfloat16 l0=__float2bfloat16(f.x-__bfloat162float(h0));
    __nv_bfloat16 l1=__float2bfloat16(f.y-__bfloat162float(h1));
    __nv_bfloat16 l2=__float2bfloat16(f.z-__bfloat162float(h2));
    __nv_bfloat16 l3=__float2bfloat16(f.w-__bfloat162float(h3));
    __nv_bfloat162* H = (__nv_bfloat162*)hi;
    __nv_bfloat162* L = (__nv_bfloat162*)lo;
    H[i*2]   = __nv_bfloat162(h0,h1);  H[i*2+1] = __nv_bfloat162(h2,h3);
    L[i*2]   = __nv_bfloat162(l0,l1);  L[i*2+1] = __nv_bfloat162(l2,l3);
}

// ============================================================
// Kernel 1: QKV projections on tensor pipe. O = X @ W^T, bf16x3 split.
// block tile 128x64, 8 warps (warp 32x32), BK=32.
// smem rows padded to 40 bf16 (80B) -> conflict-free fragment LDS.
// ============================================================
#define ASTR 40
__global__ __launch_bounds__(256) void proj_kernel(){
    int z = blockIdx.z;
    const __nv_bfloat16* Ah_g = (z==0) ? g_qh : g_kh;
    const __nv_bfloat16* Al_g = (z==0) ? g_ql : g_kl;
    const __nv_bfloat16* Bh_g = g_wh + z*DIM*DIM;
    const __nv_bfloat16* Bl_g = g_wl + z*DIM*DIM;
    float* O = (z==0) ? g_q : (z==1 ? g_k : g_v);
    bool act = (z < 2);

    __shared__ __nv_bfloat16 Ah[128*ASTR], Al[128*ASTR];
    __shared__ __nv_bfloat16 Bh[64*ASTR],  Bl[64*ASTR];

    int tid = threadIdx.x;
    int wid = tid >> 5, lane = tid & 31;
    int wm = wid & 3, wn = wid >> 2;          // 4 x 2 warps
    int g = lane >> 2, tg = lane & 3;
    int m0 = blockIdx.y*128, n0 = blockIdx.x*64;

    const u32* Ah32 = (const u32*)Ah;  const u32* Al32 = (const u32*)Al;
    const u32* Bh32 = (const u32*)Bh;  const u32* Bl32 = (const u32*)Bl;

    float acc[2][4][4];   // [mt][nt][frag]
    #pragma unroll
    for (int mt=0; mt<2; mt++)
        #pragma unroll
        for (int nt=0; nt<4; nt++)
            #pragma unroll
            for (int e=0; e<4; e++) acc[mt][nt][e] = 0.f;

    // fill indices
    int ar = tid >> 1, ahalf = (tid & 1)*8;       // A: row, word-offset {0,8}
    int br = tid >> 2, bq = (tid & 3)*4;          // B: row, word-offset {0,4,8,12}

    for (int kt = 0; kt < DIM; kt += 32){
        __syncthreads();
        {   // A tiles: 128 x 32 bf16 (hi & lo)
            const uint4* sh = (const uint4*)(Ah_g + (m0+ar)*DIM + kt + ahalf*2);
            const uint4* sl = (const uint4*)(Al_g + (m0+ar)*DIM + kt + ahalf*2);
            uint4* dh = (uint4*)((u32*)Ah + ar*(ASTR/2) + ahalf);
            uint4* dl = (uint4*)((u32*)Al + ar*(ASTR/2) + ahalf);
            dh[0]=sh[0]; dh[1]=sh[1]; dl[0]=sl[0]; dl[1]=sl[1];
            // B tiles: 64 x 32 bf16
            const uint4* th = (const uint4*)(Bh_g + (n0+br)*DIM + kt + bq*2);
            const uint4* tl = (const uint4*)(Bl_g + (n0+br)*DIM + kt + bq*2);
            ((uint4*)((u32*)Bh + br*(ASTR/2) + bq))[0] = th[0];
            ((uint4*)((u32*)Bl + br*(ASTR/2) + bq))[0] = tl[0];
        }
        __syncthreads();

        #pragma unroll
        for (int ks = 0; ks < 2; ks++){
            int kw = ks*8 + tg;
            u32 ah[2][4], al[2][4];
            #pragma unroll
            for (int mt=0; mt<2; mt++){
                int r0 = (wm*32 + mt*16 + g)*(ASTR/2);
                int r8 = r0 + 8*(ASTR/2);
                ah[mt][0]=Ah32[r0+kw]; ah[mt][1]=Ah32[r8+kw];
                ah[mt][2]=Ah32[r0+kw+4]; ah[mt][3]=Ah32[r8+kw+4];
                al[mt][0]=Al32[r0+kw]; al[mt][1]=Al32[r8+kw];
                al[mt][2]=Al32[r0+kw+4]; al[mt][3]=Al32[r8+kw+4];
            }
            #pragma unroll
            for (int nt=0; nt<4; nt++){
                int nr = (wn*32 + nt*8 + g)*(ASTR/2);
                u32 bh0=Bh32[nr+kw], bh1=Bh32[nr+kw+4];
                u32 bl0=Bl32[nr+kw], bl1=Bl32[nr+kw+4];
                #pragma unroll
                for (int mt=0; mt<2; mt++){
                    mma_bf16(acc[mt][nt], ah[mt][0],ah[mt][1],ah[mt][2],ah[mt][3], bh0,bh1);
                    mma_bf16(acc[mt][nt], ah[mt][0],ah[mt][1],ah[mt][2],ah[mt][3], bl0,bl1);
                    mma_bf16(acc[mt][nt], al[mt][0],al[mt][1],al[mt][2],al[mt][3], bh0,bh1);
                }
            }
        }
    }

    // epilogue
    #pragma unroll
    for (int mt=0; mt<2; mt++){
        #pragma unroll
        for (int nt=0; nt<4; nt++){
            int row0 = m0 + wm*32 + mt*16 + g;
            int c = n0 + wn*32 + nt*8 + tg*2;
            float v0=acc[mt][nt][0], v1=acc[mt][nt][1];
            float v2=acc[mt][nt][2], v3=acc[mt][nt][3];
            if (act){ v0=softplus_f(v0); v1=softplus_f(v1); v2=softplus_f(v2); v3=softplus_f(v3); }
            *(float2*)(O + row0*DIM + c)     = make_float2(v0,v1);
            *(float2*)(O + (row0+8)*DIM + c) = make_float2(v2,v3);
        }
    }
}

// ============================================================
// Kernel 2: per-chunk state (UNCHANGED from R10 winner)
// ============================================================
__global__ __launch_bounds__(256) void chunk_kv_kernel(){
    int bid = blockIdx.x;
    int head = bid >> 5, chunk = bid & 31;
    int n = head >> 3, h = head & 7;
    int row0 = n*LSEQ + chunk*CHUNK;
    int col  = h*HD;

    __shared__ float Ks[64*68];
    __shared__ float Vs[64*68];
    int tid = threadIdx.x;
    {
        int r = tid >> 2, c0 = (tid & 3)*16;
        const float* kr = g_k + (row0+r)*DIM + col;
        const float* vr = g_v + (row0+r)*DIM + col;
        #pragma unroll
        for (int t = 0; t < 4; t++){
            *(float4*)&Ks[r*68 + c0 + t*4] = *(const float4*)(kr + c0 + t*4);
            *(float4*)&Vs[r*68 + c0 + t*4] = *(const float4*)(vr + c0 + t*4);
        }
    }
    __syncthreads();

    int ty = tid >> 4, tx = tid & 15;
    int ty4 = ty*4, tx4 = tx*4;

    ull acc[4][2] = {};
    #pragma unroll 8
    for (int j = 0; j < 64; j++){
        ull b01 = *(const ull*)&Vs[j*68 + tx4];
        ull b23 = *(const ull*)&Vs[j*68 + tx4 + 2];
        #pragma unroll
        for (int i = 0; i < 4; i++){
            float av = Ks[j*68 + ty4 + i];
            ull a2 = pack2(av, av);
            fma2(acc[i][0], a2, b01);
            fma2(acc[i][1], a2, b23);
        }
    }

    float* Sp = g_S + (head*NCH + chunk)*SSIZE;
    #pragma unroll
    for (int i = 0; i < 4; i++){
        float2 v01 = unpack2(acc[i][0]);
        float2 v23 = unpack2(acc[i][1]);
        float* row = Sp + (ty4+i)*SROW + tx4;
        row[0]=v01.x; row[1]=v01.y; row[2]=v23.x; row[3]=v23.y;
    }
    if (tid < 64){
        float s = 0.f;
        #pragma unroll 8
        for (int j = 0; j < 64; j++) s += Ks[j*68 + tid];
        Sp[tid*SROW + 64] = s;
    }
}

// ============================================================
// Kernel 3: exclusive prefix scan (UNCHANGED from R10 winner)
// ============================================================
__global__ __launch_bounds__(256) void scan_kernel(){
    int head = blockIdx.x / 17, part = blockIdx.x % 17;
    int e = part*256 + threadIdx.x;
    float* base = g_S + head*NCH*SSIZE + e;
    float vals[NCH];
    #pragma unroll
    for (int c = 0; c < NCH; c++) vals[c] = base[c*SSIZE];
    float run = 0.f;
    #pragma unroll
    for (int c = 0; c < NCH; c++){ base[c*SSIZE] = run; run += vals[c]; }
}

// ============================================================
// Kernel 4: attention output (UNCHANGED from R10 winner)
// ============================================================
#define ATT_SMEM ((3*SSIZE + 64)*4)

__global__ __launch_bounds__(256) void attn_kernel(float* __restrict__ out){
    extern __shared__ float U[];
    float* PT = U;
    float* BA = U + SSIZE;
    float* BV = U + 2*SSIZE;
    float* zq = U + 3*SSIZE;

    int bid = blockIdx.x;
    int head = bid >> 5, chunk = bid & 31;
    int n = head >> 3, h = head & 7;
    int row0 = n*LSEQ + chunk*CHUNK;
    int col  = h*HD;

    int tid = threadIdx.x;
    int ty = tid >> 4, tx = tid & 15;
    int ty4 = ty*4, tx4 = tx*4;

    {
        int r = tid & 63, cb = (tid >> 6)*16;
        const float* qrow = g_q + (row0+r)*DIM + col + cb;
        #pragma unroll
        for (int t = 0; t < 4; t++){
            float4 f = *(const float4*)(qrow + t*4);
            int c = cb + t*4;
            PT[(c+0)*68+r]=f.x; PT[(c+1)*68+r]=f.y;
            PT[(c+2)*68+r]=f.z; PT[(c+3)*68+r]=f.w;
        }
    }
    {
        const float* Sp = g_S + (head*NCH + chunk)*SSIZE;
        for (int e = tid*4; e < SSIZE; e += 1024)
            *(float4*)&BA[e] = *(const float4*)&Sp[e];
    }
    __syncthreads();

    ull acc[4][2] = {};
    #pragma unroll 8
    for (int d = 0; d < 64; d++){
        ull b01 = *(const ull*)&BA[d*68 + tx4];
        ull b23 = *(const ull*)&BA[d*68 + tx4 + 2];
        #pragma unroll
        for (int i = 0; i < 4; i++){
            float av = PT[d*68 + ty4 + i];
            ull a2 = pack2(av, av);
            fma2(acc[i][0], a2, b01);
            fma2(acc[i][1], a2, b23);
        }
    }
    if (tid < 64){
        float s = 0.f;
        #pragma unroll 8
        for (int d = 0; d < 64; d++) s += PT[d*68 + tid] * BA[d*68 + 64];
        zq[tid] = s;
    }
    __syncthreads();

    {
        int r = tid & 63, cb = (tid >> 6)*16;
        const float* krow = g_k + (row0+r)*DIM + col + cb;
        #pragma unroll
        for (int t = 0; t < 4; t++){
            float4 f = *(const float4*)(krow + t*4);
            int c = cb + t*4;
            BA[(c+0)*68+r]=f.x; BA[(c+1)*68+r]=f.y;
            BA[(c+2)*68+r]=f.z; BA[(c+3)*68+r]=f.w;
        }
        int r2 = tid >> 2, c2 = (tid & 3)*16;
        const float* vrow = g_v + (row0+r2)*DIM + col;
        #pragma unroll
        for (int t = 0; t < 4; t++)
            *(float4*)&BV[r2*68 + c2 + t*4] = *(const float4*)(vrow + c2 + t*4);
    }
    __syncthreads();

    ull accb[4][2] = {};
    #pragma unroll 8
    for (int d = 0; d < 64; d++){
        ull b01 = *(const ull*)&BA[d*68 + tx4];
        ull b23 = *(const ull*)&BA[d*68 + tx4 + 2];
        #pragma unroll
        for (int i = 0; i < 4; i++){
            float av = PT[d*68 + ty4 + i];
            ull a2 = pack2(av, av);
            fma2(accb[i][0], a2, b01);
            fma2(accb[i][1], a2, b23);
        }
    }
    __syncthreads();

    #pragma unroll
    for (int i = 0; i < 4; i++){
        float2 v01 = unpack2(accb[i][0]);
        float2 v23 = unpack2(accb[i][1]);
        float vv[4] = {v01.x, v01.y, v23.x, v23.y};
        int q = ty4 + i;
        #pragma unroll
        for (int jj = 0; jj < 4; jj++){
            int j = tx4 + jj;
            PT[j*68 + q] = (j <= q) ? vv[jj] : 0.f;
        }
    }
    __syncthreads();
    if (tid < 64){
        float s = 0.f;
        #pragma unroll 8
        for (int j = 0; j < 64; j++) s += PT[j*68 + tid];
        zq[tid] += s;
    }
    __syncthreads();

    #pragma unroll 8
    for (int j = 0; j < 64; j++){
        ull b01 = *(const ull*)&BV[j*68 + tx4];
        ull b23 = *(const ull*)&BV[j*68 + tx4 + 2];
        #pragma unroll
        for (int i = 0; i < 4; i++){
            float av = PT[j*68 + ty4 + i];
            ull a2 = pack2(av, av);
            fma2(acc[i][0], a2, b01);
            fma2(acc[i][1], a2, b23);
        }
    }

    #pragma unroll
    for (int i = 0; i < 4; i++){
        int q = ty4 + i;
        float inv = 1.0f / zq[q];
        float2 v01 = unpack2(acc[i][0]);
        float2 v23 = unpack2(acc[i][1]);
        float* orow = out + (row0+q)*DIM + col + tx4;
        orow[0]=v01.x*inv; orow[1]=v01.y*inv; orow[2]=v23.x*inv; orow[3]=v23.y*inv;
    }
}

extern "C" void kernel_launch(void* const* d_in, const int* in_sizes, int n_in,
                              void* d_out, int out_size){
    const float* query  = (const float*)d_in[0];
    const float* keyseq = (const float*)d_in[1];
    const float* Wq     = (const float*)d_in[2];
    const float* Wk     = (const float*)d_in[3];
    const float* Wv     = (const float*)d_in[4];
    float* out = (float*)d_out;

    cudaFuncSetAttribute(attn_kernel, cudaFuncAttributeMaxDynamicSharedMemorySize, ATT_SMEM);

    __nv_bfloat16 *qh, *ql, *kh, *kl, *wh, *wl;
    cudaGetSymbolAddress((void**)&qh, g_qh); cudaGetSymbolAddress((void**)&ql, g_ql);
    cudaGetSymbolAddress((void**)&kh, g_kh); cudaGetSymbolAddress((void**)&kl, g_kl);
    cudaGetSymbolAddress((void**)&wh, g_wh); cudaGetSymbolAddress((void**)&wl, g_wl);

    cvt_kernel<<<(MROWS*DIM/4+255)/256, 256>>>(query,  qh, ql, MROWS*DIM/4);
    cvt_kernel<<<(MROWS*DIM/4+255)/256, 256>>>(keyseq, kh, kl, MROWS*DIM/4);
    cvt_kernel<<<(DIM*DIM/4+255)/256, 256>>>(Wq, wh,            wl,            DIM*DIM/4);
    cvt_kernel<<<(DIM*DIM/4+255)/256, 256>>>(Wk, wh+DIM*DIM,   wl+DIM*DIM,   DIM*DIM/4);
    cvt_kernel<<<(DIM*DIM/4+255)/256, 256>>>(Wv, wh+2*DIM*DIM, wl+2*DIM*DIM, DIM*DIM/4);

    dim3 g1(DIM/64, MROWS/128, 3);
    proj_kernel<<<g1, 256>>>();
    chunk_kv_kernel<<<NHEAD*NCH, 256>>>();
    scan_kernel<<<NHEAD*17, 256>>>();
    attn_kernel<<<NHEAD*NCH, 256, ATT_SMEM>>>(out);
}